// round 1
// baseline (speedup 1.0000x reference)
#include <cuda_runtime.h>

#define BATCH_TOT 524288
#define KDIM 128
#define NDIM 128
#define XS_PITCH 65   // ull per row (64 data + 1 pad) -> avoids 32-way bank conflicts in quad pass

typedef unsigned long long ull;

__device__ __forceinline__ ull ffma2(ull a, ull b, ull c) {
    ull d;
    asm("fma.rn.f32x2 %0, %1, %2, %3;" : "=l"(d) : "l"(a), "l"(b), "l"(c));
    return d;
}
__device__ __forceinline__ float lo32(ull v) { return __uint_as_float((unsigned)(v & 0xffffffffu)); }
__device__ __forceinline__ float hi32(ull v) { return __uint_as_float((unsigned)(v >> 32)); }

// Fused kernel: per block handles 128 rows of x.
//  - mu = x @ W + b_mu      (f32x2-packed SGEMM, 8x8 register tile per thread)
//  - quad[r] = sum_k x[r][k]^2 * softplus(w_sigma)[k]
//  - sigma[r][j] = quad[r] + softplus(b_sigma)[j]
__global__ __launch_bounds__(256, 1)
void fused_kernel(const float* __restrict__ x,
                  const float* __restrict__ w_mu,
                  const float* __restrict__ w_sigma,
                  const float* __restrict__ b_mu,
                  const float* __restrict__ b_sigma,
                  float* __restrict__ out)
{
    extern __shared__ float sm[];
    ull*   xs   = (ull*)sm;                    // [128][XS_PITCH] (64 data pairs/row)
    ull*   ws   = xs + 128 * XS_PITCH;         // [64][128] pairs: ws[kk][j]=(W[2kk][j],W[2kk+1][j])
    float* spw  = (float*)(ws + 64 * 128);     // 128
    float* spb  = spw + 128;                   // 128
    float* bmu  = spb + 128;                   // 128
    float* quad = bmu + 128;                   // 128

    const int tid = threadIdx.x;
    const int tx  = tid & 15;                  // 16 col-groups of 8
    const int ty  = tid >> 4;                  // 16 row-groups of 8
    const size_t rowBase = (size_t)blockIdx.x * 128;

    // ---- load x tile (128x128 f32 as 8192 ulls, coalesced) ----
    const ull* xg = (const ull*)(x + rowBase * KDIM);
    #pragma unroll
    for (int i = 0; i < 32; i++) {
        int idx = tid + i * 256;               // 0..8191
        int r = idx >> 6, c = idx & 63;
        xs[r * XS_PITCH + c] = xg[idx];
    }
    // ---- load W, interleave k-pairs ----
    #pragma unroll
    for (int i = 0; i < 64; i++) {
        int idx = tid + i * 256;               // 0..16383
        int k = idx >> 7, j = idx & 127;
        ((float*)ws)[(k >> 1) * 256 + 2 * j + (k & 1)] = w_mu[idx];
    }
    if (tid < 128) {
        spw[tid] = log1pf(expf(w_sigma[tid]));
        spb[tid] = log1pf(expf(b_sigma[tid]));
        bmu[tid] = b_mu[tid];
    }
    __syncthreads();

    // ---- quad: per-row weighted sum of squares ----
    if (tid < 128) {
        float q = 0.f;
        #pragma unroll
        for (int kk = 0; kk < 64; kk++) {
            ull p = xs[tid * XS_PITCH + kk];
            float a = lo32(p), b = hi32(p);
            q = fmaf(a * a, spw[2 * kk], q);
            q = fmaf(b * b, spw[2 * kk + 1], q);
        }
        quad[tid] = q;
    }
    __syncthreads();

    // ---- main GEMM: 64 packed-k steps, 8x8 f32x2 accumulators ----
    ull acc[8][8];
    #pragma unroll
    for (int i = 0; i < 8; i++)
        #pragma unroll
        for (int j = 0; j < 8; j++)
            acc[i][j] = 0ull;

    const int rbase = ty * 8;
    const int cbase = tx * 8;

    #pragma unroll 4
    for (int kk = 0; kk < 64; kk++) {
        ull af[8], bf[8];
        #pragma unroll
        for (int i = 0; i < 8; i++)
            af[i] = xs[(rbase + i) * XS_PITCH + kk];
        const ulonglong2* wrow = (const ulonglong2*)(ws + kk * 128 + cbase);
        #pragma unroll
        for (int j = 0; j < 4; j++) {
            ulonglong2 v = wrow[j];
            bf[2 * j] = v.x; bf[2 * j + 1] = v.y;
        }
        #pragma unroll
        for (int i = 0; i < 8; i++)
            #pragma unroll
            for (int j = 0; j < 8; j++)
                acc[i][j] = ffma2(af[i], bf[j], acc[i][j]);
    }

    // ---- epilogue: mu writes ----
    float bj[8];
    #pragma unroll
    for (int j = 0; j < 8; j++) bj[j] = bmu[cbase + j];

    #pragma unroll
    for (int i = 0; i < 8; i++) {
        size_t gr = rowBase + rbase + i;
        float r[8];
        #pragma unroll
        for (int j = 0; j < 8; j++)
            r[j] = lo32(acc[i][j]) + hi32(acc[i][j]) + bj[j];
        float4* o = (float4*)(out + gr * NDIM + cbase);
        o[0] = make_float4(r[0], r[1], r[2], r[3]);
        o[1] = make_float4(r[4], r[5], r[6], r[7]);
    }

    // ---- epilogue: sigma writes (cooperative, fully coalesced float4) ----
    float4* sig4 = (float4*)(out + (size_t)BATCH_TOT * NDIM + rowBase * NDIM);
    const float4* spb4 = (const float4*)spb;
    #pragma unroll
    for (int it = 0; it < 16; it++) {
        int idx4 = tid + it * 256;             // 0..4095
        int r = idx4 >> 5, c4 = idx4 & 31;
        float q = quad[r];
        float4 s = spb4[c4];
        sig4[idx4] = make_float4(q + s.x, q + s.y, q + s.z, q + s.w);
    }
}

// KL: kl = -0.5 * ( sum_j(log spw_j - spw_j) - sum|W| )
// (mean_j of 128*f_j == sum_j f_j since out==in==128; term2 is a scalar under the mean)
__global__ void kl_kernel(const float* __restrict__ w_mu,
                          const float* __restrict__ w_sigma,
                          float* __restrict__ out_kl)
{
    __shared__ float red[256];
    const int tid = threadIdx.x;
    float s = 0.f;
    for (int i = tid; i < KDIM * NDIM; i += 256) s += fabsf(w_mu[i]);
    float t = 0.f;
    if (tid < 128) {
        float spw = log1pf(expf(w_sigma[tid]));
        t = logf(spw) - spw;
    }
    red[tid] = t - s;
    __syncthreads();
    for (int off = 128; off > 0; off >>= 1) {
        if (tid < off) red[tid] += red[tid + off];
        __syncthreads();
    }
    if (tid == 0) out_kl[0] = -0.5f * red[0];
}

extern "C" void kernel_launch(void* const* d_in, const int* in_sizes, int n_in,
                              void* d_out, int out_size)
{
    const float* x       = (const float*)d_in[0];
    const float* w_mu    = (const float*)d_in[1];
    const float* w_sigma = (const float*)d_in[2];
    const float* b_mu    = (const float*)d_in[3];
    const float* b_sigma = (const float*)d_in[4];
    float* out = (float*)d_out;

    const int smem_bytes = (128 * XS_PITCH + 64 * 128) * (int)sizeof(ull) + 4 * 128 * (int)sizeof(float);
    cudaFuncSetAttribute(fused_kernel, cudaFuncAttributeMaxDynamicSharedMemorySize, smem_bytes);

    fused_kernel<<<BATCH_TOT / 128, 256, smem_bytes>>>(x, w_mu, w_sigma, b_mu, b_sigma, out);
    kl_kernel<<<1, 256>>>(w_mu, w_sigma, out + (size_t)out_size - 1);
}

// round 3
// speedup vs baseline: 1.9114x; 1.9114x over previous
#include <cuda_runtime.h>
#include <cuda_bf16.h>
#include <cstdint>

#define BATCH_TOT 524288
#define KDIM 128
#define NDIM 128

// bf16 tile: 128 rows x 128 cols, row pitch 272 bytes (17 x 16B -> ldmatrix conflict-free)
#define TPITCH 272
#define TILE_BYTES (128 * TPITCH)     // 34816

// smem layout (bytes)
#define SM_XH   0
#define SM_XL   (SM_XH + TILE_BYTES)
#define SM_WH   (SM_XL + TILE_BYTES)
#define SM_WL   (SM_WH + TILE_BYTES)
#define SM_QUAD (SM_WL + TILE_BYTES)        // 128 f32
#define SM_SPB  (SM_QUAD + 512)             // 128 f32
#define SM_TOTAL (SM_SPB + 512)             // ~140.8 KB

// global scratch written by prep kernel: W split into bf16 hi/lo, [n][k] layout, pitch 272
__device__ __align__(16) unsigned char g_whi[TILE_BYTES];
__device__ __align__(16) unsigned char g_wlo[TILE_BYTES];
__device__ float g_spw[128];
__device__ float g_spb[128];

__device__ __forceinline__ uint32_t smem_u32(const void* p) {
    uint32_t a;
    asm("{ .reg .u64 t; cvta.to.shared.u64 t, %1; cvt.u32.u64 %0, t; }" : "=r"(a) : "l"(p));
    return a;
}

__device__ __forceinline__ void ldsm_x4(uint32_t& r0, uint32_t& r1, uint32_t& r2, uint32_t& r3,
                                        uint32_t addr) {
    asm volatile("ldmatrix.sync.aligned.m8n8.x4.shared.b16 {%0,%1,%2,%3}, [%4];"
                 : "=r"(r0), "=r"(r1), "=r"(r2), "=r"(r3) : "r"(addr));
}

__device__ __forceinline__ void mma_bf16(float& c0, float& c1, float& c2, float& c3,
                                         uint32_t a0, uint32_t a1, uint32_t a2, uint32_t a3,
                                         uint32_t b0, uint32_t b1) {
    asm volatile(
        "mma.sync.aligned.m16n8k16.row.col.f32.bf16.bf16.f32 "
        "{%0,%1,%2,%3}, {%4,%5,%6,%7}, {%8,%9}, {%0,%1,%2,%3};"
        : "+f"(c0), "+f"(c1), "+f"(c2), "+f"(c3)
        : "r"(a0), "r"(a1), "r"(a2), "r"(a3), "r"(b0), "r"(b1));
}

// ---------------- prep kernel: split W -> bf16 hi/lo, transpose to [n][k], softplus, KL ----------
__global__ __launch_bounds__(1024)
void prep_kernel(const float* __restrict__ w_mu, const float* __restrict__ w_sigma,
                 const float* __restrict__ b_sigma, float* __restrict__ out_kl)
{
    __shared__ float red[1024];
    const int tid = threadIdx.x;
    float s = 0.f;
    #pragma unroll
    for (int i = 0; i < 16; i++) {
        int idx = tid + i * 1024;            // idx = k*128 + n
        float w = w_mu[idx];
        s += fabsf(w);
        int k = idx >> 7, n = idx & 127;
        __nv_bfloat16 hi = __float2bfloat16(w);
        __nv_bfloat16 lo = __float2bfloat16(w - __bfloat162float(hi));
        int off = n * TPITCH + k * 2;        // B[n][k] = W[k][n]
        *(__nv_bfloat16*)(g_whi + off) = hi;
        *(__nv_bfloat16*)(g_wlo + off) = lo;
    }
    float t = 0.f;
    if (tid < 128) {
        float spw = log1pf(expf(w_sigma[tid]));
        g_spw[tid] = spw;
        t = logf(spw) - spw;                 // 128 * mean_j == sum_j
        g_spb[tid] = log1pf(expf(b_sigma[tid]));
    }
    red[tid] = t - s;
    __syncthreads();
    for (int o = 512; o > 0; o >>= 1) {
        if (tid < o) red[tid] += red[tid + o];
        __syncthreads();
    }
    if (tid == 0) out_kl[0] = -0.5f * red[0];
}

// ---------------- main fused kernel: one CTA = 128 batch rows, 8 warps x (16 x 128) HMMA --------
__global__ __launch_bounds__(256, 1)
void fused_kernel(const float* __restrict__ x, const float* __restrict__ b_mu,
                  float* __restrict__ out)
{
    extern __shared__ __align__(16) unsigned char smem[];
    const uint32_t sbase = smem_u32(smem);
    const int tid = threadIdx.x, wid = tid >> 5, lane = tid & 31;
    const size_t rowBase = (size_t)blockIdx.x * 128;

    // ---- W tiles: pre-split global -> smem (L2-resident broadcast) ----
    {
        const float4* sh = (const float4*)g_whi;
        const float4* sl = (const float4*)g_wlo;
        float4* dh = (float4*)(smem + SM_WH);
        float4* dl = (float4*)(smem + SM_WL);
        #pragma unroll
        for (int i = 0; i < 8; i++) {        // 8*256 = 2048 < 2176 float4
            int idx = tid + i * 256;
            dh[idx] = sh[idx];
            dl[idx] = sl[idx];
        }
        if (tid < 128) {                     // tail 2176-2048 = 128
            int idx = 2048 + tid;
            dh[idx] = sh[idx];
            dl[idx] = sl[idx];
        }
    }
    if (tid < 128) ((float*)(smem + SM_SPB))[tid] = g_spb[tid];

    // ---- x -> xh/xl bf16 tiles + per-row quad (2 threads per row) ----
    {
        const int row = tid >> 1, half = tid & 1;
        const float4* xr = (const float4*)(x + rowBase * KDIM + row * KDIM + half * 64);
        const float4* spw4 = (const float4*)(g_spw) + half * 16;
        unsigned char* xh = smem + SM_XH + row * TPITCH + half * 128;
        unsigned char* xl = smem + SM_XL + row * TPITCH + half * 128;
        float q = 0.f;
        #pragma unroll
        for (int i = 0; i < 16; i++) {
            float4 v = xr[i];
            float4 w = spw4[i];
            q = fmaf(v.x * v.x, w.x, q);
            q = fmaf(v.y * v.y, w.y, q);
            q = fmaf(v.z * v.z, w.z, q);
            q = fmaf(v.w * v.w, w.w, q);
            __nv_bfloat16 h0 = __float2bfloat16(v.x), h1 = __float2bfloat16(v.y);
            __nv_bfloat16 h2 = __float2bfloat16(v.z), h3 = __float2bfloat16(v.w);
            __nv_bfloat16 l0 = __float2bfloat16(v.x - __bfloat162float(h0));
            __nv_bfloat16 l1 = __float2bfloat16(v.y - __bfloat162float(h1));
            __nv_bfloat16 l2 = __float2bfloat16(v.z - __bfloat162float(h2));
            __nv_bfloat16 l3 = __float2bfloat16(v.w - __bfloat162float(h3));
            uint32_t uh0 = ((uint32_t)__bfloat16_as_ushort(h1) << 16) | __bfloat16_as_ushort(h0);
            uint32_t uh1 = ((uint32_t)__bfloat16_as_ushort(h3) << 16) | __bfloat16_as_ushort(h2);
            uint32_t ul0 = ((uint32_t)__bfloat16_as_ushort(l1) << 16) | __bfloat16_as_ushort(l0);
            uint32_t ul1 = ((uint32_t)__bfloat16_as_ushort(l3) << 16) | __bfloat16_as_ushort(l2);
            *(uint2*)(xh + i * 8) = make_uint2(uh0, uh1);
            *(uint2*)(xl + i * 8) = make_uint2(ul0, ul1);
        }
        q += __shfl_xor_sync(0xffffffffu, q, 1);
        if (half == 0) ((float*)(smem + SM_QUAD))[row] = q;
    }
    __syncthreads();

    // ---- GEMM: 3 bf16-split passes on mma.sync m16n8k16 ----
    float acc[16][4];
    #pragma unroll
    for (int t = 0; t < 16; t++)
        #pragma unroll
        for (int j = 0; j < 4; j++) acc[t][j] = 0.f;

    const int m0 = wid * 16;
    // A frag lane address: row = m0 + lane%16, col-bytes = (lane/16)*16  (+ kc*32)
    const uint32_t a_lane = (uint32_t)((m0 + (lane & 15)) * TPITCH + (lane >> 4) * 16);
    // B frag lane address: n = (lane>>4)*8 + (lane&7), k-bytes = ((lane>>3)&1)*16 (+ nt*16*TPITCH + kc*32)
    const uint32_t b_lane = (uint32_t)(((lane >> 4) * 8 + (lane & 7)) * TPITCH + ((lane >> 3) & 1) * 16);

    #pragma unroll
    for (int pass = 0; pass < 3; pass++) {
        const uint32_t abase = sbase + ((pass == 1) ? SM_XL : SM_XH) + a_lane;
        const uint32_t bbase = sbase + ((pass == 2) ? SM_WL : SM_WH) + b_lane;
        #pragma unroll
        for (int kc = 0; kc < 8; kc++) {
            uint32_t a0, a1, a2, a3;
            ldsm_x4(a0, a1, a2, a3, abase + kc * 32);
            #pragma unroll
            for (int nt = 0; nt < 8; nt++) {
                uint32_t b0, b1, b2, b3;
                ldsm_x4(b0, b1, b2, b3, bbase + nt * (16 * TPITCH) + kc * 32);
                mma_bf16(acc[nt * 2][0], acc[nt * 2][1], acc[nt * 2][2], acc[nt * 2][3],
                         a0, a1, a2, a3, b0, b1);
                mma_bf16(acc[nt * 2 + 1][0], acc[nt * 2 + 1][1], acc[nt * 2 + 1][2], acc[nt * 2 + 1][3],
                         a0, a1, a2, a3, b2, b3);
            }
        }
    }

    // ---- epilogue: mu directly from fragments ----
    {
        const int g = lane >> 2, tig = lane & 3;
        float* o0 = out + (rowBase + m0 + g) * NDIM;
        float* o1 = o0 + 8 * NDIM;
        #pragma unroll
        for (int t = 0; t < 16; t++) {
            int col = t * 8 + 2 * tig;
            float2 bm = __ldg((const float2*)(b_mu + col));
            *(float2*)(o0 + col) = make_float2(acc[t][0] + bm.x, acc[t][1] + bm.y);
            *(float2*)(o1 + col) = make_float2(acc[t][2] + bm.x, acc[t][3] + bm.y);
        }
    }

    // ---- epilogue: sigma (coalesced float4) ----
    {
        const float* quad = (const float*)(smem + SM_QUAD);
        const float4* spb4 = (const float4*)(smem + SM_SPB);
        float4* sg = (float4*)(out + (size_t)BATCH_TOT * NDIM + rowBase * NDIM);
        #pragma unroll
        for (int i = 0; i < 16; i++) {
            int idx = tid + i * 256;             // float4 index 0..4095
            int r = idx >> 5, c4 = idx & 31;
            float q = quad[r];
            float4 s = spb4[c4];
            sg[idx] = make_float4(q + s.x, q + s.y, q + s.z, q + s.w);
        }
    }
}

extern "C" void kernel_launch(void* const* d_in, const int* in_sizes, int n_in,
                              void* d_out, int out_size)
{
    const float* x       = (const float*)d_in[0];
    const float* w_mu    = (const float*)d_in[1];
    const float* w_sigma = (const float*)d_in[2];
    const float* b_mu    = (const float*)d_in[3];
    const float* b_sigma = (const float*)d_in[4];
    float* out = (float*)d_out;

    cudaFuncSetAttribute(fused_kernel, cudaFuncAttributeMaxDynamicSharedMemorySize, SM_TOTAL);

    prep_kernel<<<1, 1024>>>(w_mu, w_sigma, b_sigma, out + (size_t)out_size - 1);
    fused_kernel<<<BATCH_TOT / 128, 256, SM_TOTAL>>>(x, b_mu, out);
}

// round 4
// speedup vs baseline: 2.2894x; 1.1978x over previous
#include <cuda_runtime.h>
#include <cuda_bf16.h>
#include <cstdint>

#define BATCH_TOT 524288
#define KDIM 128
#define NDIM 128
#define CHUNK_ROWS 64
#define NCHUNKS (BATCH_TOT / CHUNK_ROWS)   // 8192

// bf16 tiles, row pitch 272 bytes (17 x 16B) -> conflict-free ldmatrix
#define TPITCH 272
#define WTILE_BYTES (128 * TPITCH)         // 34816
#define XTILE_BYTES (CHUNK_ROWS * TPITCH)  // 17408

// smem layout (bytes)
#define SM_WH   0
#define SM_WL   (SM_WH + WTILE_BYTES)
#define SM_XH   (SM_WL + WTILE_BYTES)
#define SM_XL   (SM_XH + XTILE_BYTES)
#define SM_QUAD (SM_XL + XTILE_BYTES)      // 64 f32
#define SM_SPB  (SM_QUAD + 256)            // 128 f32
#define SM_SPW  (SM_SPB + 512)             // 128 f32
#define SM_TOTAL (SM_SPW + 512)            // 105,728 B -> 2 CTAs/SM

// global scratch written by prep kernel
__device__ __align__(16) unsigned char g_whi[WTILE_BYTES];
__device__ __align__(16) unsigned char g_wlo[WTILE_BYTES];
__device__ float g_spw[128];
__device__ float g_spb[128];

__device__ __forceinline__ uint32_t smem_u32(const void* p) {
    uint32_t a;
    asm("{ .reg .u64 t; cvta.to.shared.u64 t, %1; cvt.u32.u64 %0, t; }" : "=r"(a) : "l"(p));
    return a;
}
__device__ __forceinline__ void ldsm_x4(uint32_t& r0, uint32_t& r1, uint32_t& r2, uint32_t& r3,
                                        uint32_t addr) {
    asm volatile("ldmatrix.sync.aligned.m8n8.x4.shared.b16 {%0,%1,%2,%3}, [%4];"
                 : "=r"(r0), "=r"(r1), "=r"(r2), "=r"(r3) : "r"(addr));
}
__device__ __forceinline__ void mma_bf16(float* c, const uint32_t* a, uint32_t b0, uint32_t b1) {
    asm volatile(
        "mma.sync.aligned.m16n8k16.row.col.f32.bf16.bf16.f32 "
        "{%0,%1,%2,%3}, {%4,%5,%6,%7}, {%8,%9}, {%0,%1,%2,%3};"
        : "+f"(c[0]), "+f"(c[1]), "+f"(c[2]), "+f"(c[3])
        : "r"(a[0]), "r"(a[1]), "r"(a[2]), "r"(a[3]), "r"(b0), "r"(b1));
}

// ---------- prep: split W -> bf16 hi/lo [n][k] pitch 272, softplus params, KL scalar ----------
__global__ __launch_bounds__(1024)
void prep_kernel(const float* __restrict__ w_mu, const float* __restrict__ w_sigma,
                 const float* __restrict__ b_sigma, float* __restrict__ out_kl)
{
    __shared__ float red[1024];
    const int tid = threadIdx.x;
    float s = 0.f;
    #pragma unroll
    for (int i = 0; i < 16; i++) {
        int idx = tid + i * 1024;            // idx = k*128 + n
        float w = w_mu[idx];
        s += fabsf(w);
        int k = idx >> 7, n = idx & 127;
        __nv_bfloat16 hi = __float2bfloat16(w);
        __nv_bfloat16 lo = __float2bfloat16(w - __bfloat162float(hi));
        int off = n * TPITCH + k * 2;        // B[n][k] = W[k][n]
        *(__nv_bfloat16*)(g_whi + off) = hi;
        *(__nv_bfloat16*)(g_wlo + off) = lo;
    }
    float t = 0.f;
    if (tid < 128) {
        float spw = log1pf(expf(w_sigma[tid]));
        g_spw[tid] = spw;
        t = logf(spw) - spw;                 // 128 * mean_j == sum_j
        g_spb[tid] = log1pf(expf(b_sigma[tid]));
    }
    red[tid] = t - s;
    __syncthreads();
    for (int o = 512; o > 0; o >>= 1) {
        if (tid < o) red[tid] += red[tid + o];
        __syncthreads();
    }
    if (tid == 0) out_kl[0] = -0.5f * red[0];
}

// ---------- fused persistent kernel: 128 threads, 2 CTAs/SM, 64-row chunks ----------
__global__ __launch_bounds__(128, 2)
void fused_kernel(const float* __restrict__ x, const float* __restrict__ b_mu,
                  float* __restrict__ out)
{
    extern __shared__ __align__(16) unsigned char smem[];
    const uint32_t sbase = smem_u32(smem);
    const int tid = threadIdx.x, wid = tid >> 5, lane = tid & 31;

    // ---- one-time: W tiles global->smem, params ----
    {
        const float4* sh = (const float4*)g_whi;
        const float4* sl = (const float4*)g_wlo;
        float4* dh = (float4*)(smem + SM_WH);
        float4* dl = (float4*)(smem + SM_WL);
        #pragma unroll
        for (int i = 0; i < 17; i++) {       // 17*128 = 2176 float4
            int idx = tid + i * 128;
            dh[idx] = sh[idx];
            dl[idx] = sl[idx];
        }
    }
    if (tid < 128) {
        ((float*)(smem + SM_SPW))[tid] = g_spw[tid];
        ((float*)(smem + SM_SPB))[tid] = g_spb[tid];
    }

    // warp tile: m0 rows, n0 cols
    const int m0 = (wid >> 1) * 32;
    const int n0 = (wid & 1) * 64;
    const int g = lane >> 2, tig = lane & 3;

    // b_mu fragment (col = n0 + t*8 + 2*tig), loaded once
    float2 bm[8];
    #pragma unroll
    for (int t = 0; t < 8; t++) bm[t] = __ldg((const float2*)(b_mu + n0 + t * 8 + 2 * tig));

    // ldmatrix lane addresses
    const uint32_t a_lane = sbase + (uint32_t)((m0 + (lane & 15)) * TPITCH + (lane >> 4) * 16);
    const uint32_t b_lane = sbase + (uint32_t)((n0 + (lane >> 4) * 8 + (lane & 7)) * TPITCH +
                                               ((lane >> 3) & 1) * 16);
    const int row = tid >> 1, half = tid & 1;   // convert-phase mapping (2 threads/row)

    __syncthreads();

    for (int chunk = blockIdx.x; chunk < NCHUNKS; chunk += gridDim.x) {
        const size_t rowBase = (size_t)chunk * CHUNK_ROWS;

        // ---- convert x -> xh/xl bf16 tiles + per-row quad ----
        {
            const float4* xr = (const float4*)(x + (rowBase + row) * KDIM + half * 64);
            const float* spw = (const float*)(smem + SM_SPW) + half * 64;
            unsigned char* xh = smem + SM_XH + row * TPITCH + half * 128;
            unsigned char* xl = smem + SM_XL + row * TPITCH + half * 128;
            float q = 0.f;
            #pragma unroll
            for (int i = 0; i < 16; i++) {
                float4 v = xr[i];
                q = fmaf(v.x * v.x, spw[4 * i + 0], q);
                q = fmaf(v.y * v.y, spw[4 * i + 1], q);
                q = fmaf(v.z * v.z, spw[4 * i + 2], q);
                q = fmaf(v.w * v.w, spw[4 * i + 3], q);
                __nv_bfloat16 h0 = __float2bfloat16(v.x), h1 = __float2bfloat16(v.y);
                __nv_bfloat16 h2 = __float2bfloat16(v.z), h3 = __float2bfloat16(v.w);
                __nv_bfloat16 l0 = __float2bfloat16(v.x - __bfloat162float(h0));
                __nv_bfloat16 l1 = __float2bfloat16(v.y - __bfloat162float(h1));
                __nv_bfloat16 l2 = __float2bfloat16(v.z - __bfloat162float(h2));
                __nv_bfloat16 l3 = __float2bfloat16(v.w - __bfloat162float(h3));
                uint32_t uh0 = ((uint32_t)__bfloat16_as_ushort(h1) << 16) | __bfloat16_as_ushort(h0);
                uint32_t uh1 = ((uint32_t)__bfloat16_as_ushort(h3) << 16) | __bfloat16_as_ushort(h2);
                uint32_t ul0 = ((uint32_t)__bfloat16_as_ushort(l1) << 16) | __bfloat16_as_ushort(l0);
                uint32_t ul1 = ((uint32_t)__bfloat16_as_ushort(l3) << 16) | __bfloat16_as_ushort(l2);
                *(uint2*)(xh + i * 8) = make_uint2(uh0, uh1);
                *(uint2*)(xl + i * 8) = make_uint2(ul0, ul1);
            }
            q += __shfl_xor_sync(0xffffffffu, q, 1);
            if (half == 0) ((float*)(smem + SM_QUAD))[row] = q;
        }
        __syncthreads();

        // ---- GEMM: fused 3-term bf16 split, 32x64 warp tile ----
        float acc[2][16][4];
        #pragma unroll
        for (int mi = 0; mi < 2; mi++)
            #pragma unroll
            for (int t = 0; t < 16; t++)
                #pragma unroll
                for (int j = 0; j < 4; j++) acc[mi][t][j] = 0.f;

        #pragma unroll
        for (int kc = 0; kc < 8; kc++) {
            const uint32_t ko = kc * 32;
            uint32_t ah[2][4], al[2][4], bh[4][4], bl[4][4];
            #pragma unroll
            for (int mi = 0; mi < 2; mi++) {
                ldsm_x4(ah[mi][0], ah[mi][1], ah[mi][2], ah[mi][3],
                        a_lane + SM_XH + mi * (16 * TPITCH) + ko);
                ldsm_x4(al[mi][0], al[mi][1], al[mi][2], al[mi][3],
                        a_lane + SM_XL + mi * (16 * TPITCH) + ko);
            }
            #pragma unroll
            for (int ni = 0; ni < 4; ni++) {
                ldsm_x4(bh[ni][0], bh[ni][1], bh[ni][2], bh[ni][3],
                        b_lane + SM_WH + ni * (16 * TPITCH) + ko);
                ldsm_x4(bl[ni][0], bl[ni][1], bl[ni][2], bl[ni][3],
                        b_lane + SM_WL + ni * (16 * TPITCH) + ko);
            }
            #pragma unroll
            for (int mi = 0; mi < 2; mi++)
                #pragma unroll
                for (int ni = 0; ni < 4; ni++) {
                    mma_bf16(acc[mi][ni * 4 + 0], ah[mi], bh[ni][0], bh[ni][1]);  // xh*wh
                    mma_bf16(acc[mi][ni * 4 + 1], ah[mi], bh[ni][2], bh[ni][3]);
                    mma_bf16(acc[mi][ni * 4 + 0], al[mi], bh[ni][0], bh[ni][1]);  // xl*wh
                    mma_bf16(acc[mi][ni * 4 + 1], al[mi], bh[ni][2], bh[ni][3]);
                    mma_bf16(acc[mi][ni * 4 + 0], ah[mi], bl[ni][0], bl[ni][1]);  // xh*wl
                    mma_bf16(acc[mi][ni * 4 + 1], ah[mi], bl[ni][2], bl[ni][3]);
                }
        }
        // note: acc index t = ni*4 + bhalf covers 8-col tiles 0..7 as t' = ni*2+bhalf
        // remap below uses: col tile index = ni*2 + bhalf  ->  acc[mi][ni*4 + bhalf]

        // ---- mu epilogue: fragments -> global (sector-aligned float2) ----
        #pragma unroll
        for (int mi = 0; mi < 2; mi++) {
            float* o0 = out + (rowBase + m0 + mi * 16 + g) * NDIM + n0;
            float* o1 = o0 + 8 * NDIM;
            #pragma unroll
            for (int ni = 0; ni < 4; ni++)
                #pragma unroll
                for (int h = 0; h < 2; h++) {
                    const float* c = acc[mi][ni * 4 + h];
                    int col = (ni * 2 + h) * 8 + 2 * tig;
                    float2 b = bm[ni * 2 + h];
                    *(float2*)(o0 + col) = make_float2(c[0] + b.x, c[1] + b.y);
                    *(float2*)(o1 + col) = make_float2(c[2] + b.x, c[3] + b.y);
                }
        }

        // ---- sigma epilogue: coalesced float4 ----
        {
            const float* quad = (const float*)(smem + SM_QUAD);
            const float4* spb4 = (const float4*)(smem + SM_SPB);
            float4* sg = (float4*)(out + (size_t)BATCH_TOT * NDIM + rowBase * NDIM);
            #pragma unroll
            for (int i = 0; i < 16; i++) {
                int idx = tid + i * 128;          // 0..2047 float4
                int r = idx >> 5, c4 = idx & 31;
                float q = quad[r];
                float4 s = spb4[c4];
                sg[idx] = make_float4(q + s.x, q + s.y, q + s.z, q + s.w);
            }
        }
        __syncthreads();   // xh/xl/quad reused next chunk
    }
}

extern "C" void kernel_launch(void* const* d_in, const int* in_sizes, int n_in,
                              void* d_out, int out_size)
{
    const float* x       = (const float*)d_in[0];
    const float* w_mu    = (const float*)d_in[1];
    const float* w_sigma = (const float*)d_in[2];
    const float* b_mu    = (const float*)d_in[3];
    const float* b_sigma = (const float*)d_in[4];
    float* out = (float*)d_out;

    int dev = 0, sms = 148;
    cudaGetDevice(&dev);
    cudaDeviceGetAttribute(&sms, cudaDevAttrMultiProcessorCount, dev);
    int grid = 2 * sms;
    if (grid > NCHUNKS) grid = NCHUNKS;

    cudaFuncSetAttribute(fused_kernel, cudaFuncAttributeMaxDynamicSharedMemorySize, SM_TOTAL);

    prep_kernel<<<1, 1024>>>(w_mu, w_sigma, b_sigma, out + (size_t)out_size - 1);
    fused_kernel<<<grid, 128, SM_TOTAL>>>(x, b_mu, out);
}